// round 16
// baseline (speedup 1.0000x reference)
#include <cuda_runtime.h>
#include <cuda_bf16.h>
#include <cstdint>
#include <cstddef>

// Problem sizes (fixed)
#define B_SZ   16384
#define M_SZ   3
#define D_SZ   2048
#define DH_SZ  1024
#define MTOT   (B_SZ * M_SZ)   // 49152 rows
#define NQK    (2 * DH_SZ)     // 2048 output cols (q | k)
#define NBLK   384             // 128-row blocks

// ---------------------------------------------------------------------------
// Device scratch
// ---------------------------------------------------------------------------
__device__ __nv_bfloat16 g_xhi[(size_t)MTOT * D_SZ];
__device__ __nv_bfloat16 g_xlo[(size_t)MTOT * D_SZ];
__device__ __nv_bfloat16 g_whi[(size_t)NQK * D_SZ];    // [n][k], n<1024 -> Wq, else Wk
__device__ __nv_bfloat16 g_wlo[(size_t)NQK * D_SZ];
__device__ float         g_qk [(size_t)MTOT * NQK];
__device__ float         g_wvf[D_SZ];
__device__ float         g_spart[8 * MTOT];            // partial s = x . wvf
__device__ int           g_cnt[NBLK];                  // per row-block completion

// ---------------------------------------------------------------------------
// Helpers
// ---------------------------------------------------------------------------
__device__ __forceinline__ void cp16(uint32_t dst, const void* src) {
    asm volatile("cp.async.cg.shared.global [%0], [%1], 16;\n" :: "r"(dst), "l"(src));
}
#define CP_COMMIT()  asm volatile("cp.async.commit_group;\n")
#define CP_WAIT(n)   asm volatile("cp.async.wait_group %0;\n" :: "n"(n))

#define LDSM4(R, addr)                                                          \
    asm volatile("ldmatrix.sync.aligned.m8n8.x4.shared.b16 {%0,%1,%2,%3}, [%4];"\
        : "=r"((R)[0]), "=r"((R)[1]), "=r"((R)[2]), "=r"((R)[3]) : "r"(addr))

#define MMA_BF16(C, A0, A1, A2, A3, B0, B1)                                     \
    asm volatile(                                                               \
        "mma.sync.aligned.m16n8k16.row.col.f32.bf16.bf16.f32 "                  \
        "{%0,%1,%2,%3}, {%4,%5,%6,%7}, {%8,%9}, {%0,%1,%2,%3};\n"               \
        : "+f"(C[0]), "+f"(C[1]), "+f"(C[2]), "+f"(C[3])                        \
        : "r"(A0), "r"(A1), "r"(A2), "r"(A3), "r"(B0), "r"(B1))

// ---------------------------------------------------------------------------
// Kernel 0: clear completion counters (graph-replay safety)
// ---------------------------------------------------------------------------
__global__ void clear_kernel() {
    g_cnt[threadIdx.x] = 0;
}

// ---------------------------------------------------------------------------
// Kernel 1: split concatenated weights [Wq;Wk] into bf16 hi/lo
// ---------------------------------------------------------------------------
__global__ void split_w_kernel(const float* __restrict__ Wq, const float* __restrict__ Wk) {
    int i = blockIdx.x * 256 + threadIdx.x;
    int n = i >> 11;
    int k = i & 2047;
    float w = (n < DH_SZ) ? Wq[(size_t)n * D_SZ + k]
                          : Wk[(size_t)(n - DH_SZ) * D_SZ + k];
    __nv_bfloat16 h = __float2bfloat16(w);
    g_whi[i] = h;
    g_wlo[i] = __float2bfloat16(w - __bfloat162float(h));
}

// ---------------------------------------------------------------------------
// Kernel 2: wvf[d] = sum_v Wfc[v] * Wv[v][d]
// ---------------------------------------------------------------------------
__global__ void wvf_kernel(const float* __restrict__ Wv, const float* __restrict__ Wfc) {
    int d = blockIdx.x * 256 + threadIdx.x;
    float acc = 0.f;
    for (int v = 0; v < 512; ++v)
        acc += Wfc[v] * Wv[(size_t)v * D_SZ + d];
    g_wvf[d] = acc;
}

// ---------------------------------------------------------------------------
// Kernel 3: split x into bf16 hi/lo + partial s = x . wvf per 256-float block
// ---------------------------------------------------------------------------
__global__ void split_x_kernel(const float* __restrict__ x) {
    size_t i = ((size_t)blockIdx.x * 256 + threadIdx.x) * 8;
    int lane = threadIdx.x & 31;
    float4 v0 = *(const float4*)(x + i);
    float4 v1 = *(const float4*)(x + i + 4);
    float f[8] = {v0.x, v0.y, v0.z, v0.w, v1.x, v1.y, v1.z, v1.w};
    union { uint4 u; __nv_bfloat16 b[8]; } H, L;
    int k0 = (int)(i & 2047);
    float part = 0.f;
#pragma unroll
    for (int j = 0; j < 8; ++j) {
        __nv_bfloat16 h = __float2bfloat16(f[j]);
        H.b[j] = h;
        L.b[j] = __float2bfloat16(f[j] - __bfloat162float(h));
        part += f[j] * g_wvf[k0 + j];
    }
    *(uint4*)(g_xhi + i) = H.u;
    *(uint4*)(g_xlo + i) = L.u;
#pragma unroll
    for (int off = 16; off > 0; off >>= 1)
        part += __shfl_xor_sync(0xffffffffu, part, off);
    if (lane == 0) {
        int row = (int)(i >> 11);
        g_spart[(k0 >> 8) * MTOT + row] = part;
    }
}

// ---------------------------------------------------------------------------
// Kernel 4: GEMM QK = X * W^T (3-pass bf16 split, mma.sync) + finisher Gram.
//   R15 structure (mid-iteration fill) + NEW:
//   (1) LDSM/MMA interleaved inside each K16 half (first MMA after 4 LDSM).
//   (2) Last CTA of each 128-row block grams its batches inline (L2-hot),
//       replacing the separate gram_kernel.
// ---------------------------------------------------------------------------
#define BK          32
#define NKT         (D_SZ / BK)              // 64
#define TILE_B      (128 * 64)               // one tile: 128 rows x 64B (32 bf16)
#define STAGE_B     (4 * TILE_B)             // Ahi, Alo, Bhi, Blo = 32768 B
#define SMEM_TOTAL  (3 * STAGE_B)            // 98304 B

__device__ __forceinline__ uint32_t swz(int r, int c) {
    return (uint32_t)(r * 64 + ((c ^ ((r >> 1) & 3)) << 4));
}

__global__ void __launch_bounds__(256, 2) gemm_kernel(float* __restrict__ out) {
    extern __shared__ __align__(16) char smem[];
    __shared__ int s_done;
    uint32_t sbase;
    asm("{ .reg .u64 t; cvta.to.shared.u64 t, %1; cvt.u32.u64 %0, t; }" : "=r"(sbase) : "l"(smem));

    const int tid  = threadIdx.x;
    const int warp = tid >> 5;
    const int lane = tid & 31;
    const int wm   = warp & 3;             // warp row tile (32 rows)
    const int wn   = warp >> 2;            // warp col tile (64 cols)
    const int by   = blockIdx.y;
    const int row0 = by * 128;
    const int col0 = blockIdx.x * 128;
    const int g    = lane >> 2;
    const int t2   = (lane & 3) * 2;

    const int rsubA = (lane & 7) + ((lane >> 3) & 1) * 8;
    const int cA    = lane >> 4;
    const int nsubB = (lane & 7) + ((lane >> 4) & 1) * 8;
    const int cB    = (lane >> 3) & 1;

    float c[2][8][4];
#pragma unroll
    for (int i = 0; i < 2; ++i)
#pragma unroll
        for (int j = 0; j < 8; ++j)
#pragma unroll
            for (int u = 0; u < 4; ++u) c[i][j][u] = 0.f;

    auto fill = [&](int s, int kt) {
        const int k0 = kt * BK;
        const uint32_t st = sbase + s * STAGE_B;
#pragma unroll
        for (int v = 0; v < 2; ++v) {                 // A hi+lo
            int idx = tid + v * 256;
            int r = idx >> 2, cc = idx & 3;
            uint32_t so = st + swz(r, cc);
            size_t go = (size_t)(row0 + r) * D_SZ + k0 + cc * 8;
            cp16(so,          g_xhi + go);
            cp16(so + TILE_B, g_xlo + go);
        }
#pragma unroll
        for (int v = 0; v < 2; ++v) {                 // B hi+lo
            int idx = tid + v * 256;
            int r = idx >> 2, cc = idx & 3;
            uint32_t so = st + 2 * TILE_B + swz(r, cc);
            size_t go = (size_t)(col0 + r) * D_SZ + k0 + cc * 8;
            cp16(so,          g_whi + go);
            cp16(so + TILE_B, g_wlo + go);
        }
    };

    // One K16 half with LDSM/MMA interleaved (first MMA after 4 LDSMs).
    auto compute_half = [&](int s, int c0) {
        const uint32_t sA = sbase + s * STAGE_B;
        const uint32_t sB = sA + 2 * TILE_B;
        uint32_t ahi[2][4], alo[2][4], bhi[8][2], blo[8][2];

        auto loadA = [&](int i) {
            int r = wm * 32 + i * 16 + rsubA;
            uint32_t addr = sA + swz(r, c0 + cA);
            LDSM4(ahi[i], addr);
            LDSM4(alo[i], addr + TILE_B);
        };
        auto loadB = [&](int jp) {
            int n = wn * 64 + jp * 16 + nsubB;
            uint32_t addr = sB + swz(n, c0 + cB);
            uint32_t th[4], tl[4];
            LDSM4(th, addr);
            LDSM4(tl, addr + TILE_B);
            bhi[2 * jp][0] = th[0]; bhi[2 * jp][1] = th[1];
            bhi[2 * jp + 1][0] = th[2]; bhi[2 * jp + 1][1] = th[3];
            blo[2 * jp][0] = tl[0]; blo[2 * jp][1] = tl[1];
            blo[2 * jp + 1][0] = tl[2]; blo[2 * jp + 1][1] = tl[3];
        };
        auto mma3 = [&](int i, int j) {
            MMA_BF16(c[i][j], ahi[i][0], ahi[i][1], ahi[i][2], ahi[i][3], bhi[j][0], bhi[j][1]);
            MMA_BF16(c[i][j], ahi[i][0], ahi[i][1], ahi[i][2], ahi[i][3], blo[j][0], blo[j][1]);
            MMA_BF16(c[i][j], alo[i][0], alo[i][1], alo[i][2], alo[i][3], bhi[j][0], bhi[j][1]);
        };

        loadA(0);
        loadB(0);
        mma3(0, 0); mma3(0, 1);
        loadB(1);
        mma3(0, 2); mma3(0, 3);
        loadA(1);
        mma3(1, 0); mma3(1, 1); mma3(1, 2); mma3(1, 3);
        loadB(2);
        mma3(0, 4); mma3(0, 5); mma3(1, 4); mma3(1, 5);
        loadB(3);
        mma3(0, 6); mma3(0, 7); mma3(1, 6); mma3(1, 7);
    };

    // 3-stage pipeline (R15 schedule)
    fill(0, 0); CP_COMMIT();
    fill(1, 1); CP_COMMIT();

    {   // co-resident CTA desync (R10 win)
        int bid = blockIdx.y * gridDim.x + blockIdx.x;
        if ((bid / 148) & 1) __nanosleep(1000);
    }

    for (int kt = 0; kt < NKT; ++kt) {
        CP_WAIT(1);
        __syncthreads();
        compute_half(kt % 3, 0);                        // HMMA right after barrier
        if (kt + 2 < NKT) fill((kt + 2) % 3, kt + 2);   // LSU burst mid-iteration
        CP_COMMIT();
        compute_half(kt % 3, 2);
    }

    // Epilogue 1: store accumulators
#pragma unroll
    for (int i = 0; i < 2; ++i) {
        int r = row0 + wm * 32 + i * 16 + g;
#pragma unroll
        for (int j = 0; j < 8; ++j) {
            int cb = col0 + wn * 64 + j * 8 + t2;
            *(float2*)(g_qk + (size_t)r * NQK + cb)       = make_float2(c[i][j][0], c[i][j][1]);
            *(float2*)(g_qk + (size_t)(r + 8) * NQK + cb) = make_float2(c[i][j][2], c[i][j][3]);
        }
    }

    // Epilogue 2: completion counting; last CTA of this row-block grams it.
    __syncthreads();
    if (tid == 0) {
        __threadfence();
        s_done = atomicAdd(&g_cnt[by], 1);
    }
    __syncthreads();
    if (s_done != 15) return;

    // Acquire: own block's 15 peers (via the RMW we observed) and block by-1
    // (straddling batches read up to 2 rows from it).
    if (tid == 0) {
        if (by > 0)
            while (atomicAdd(&g_cnt[by - 1], 0) < 16) __nanosleep(200);
        __threadfence();
    }
    __syncthreads();

    // Batches whose LAST row (3b+2) lies in this block: b_lo..b_hi (~42).
    const int b_lo = (128 * by) / 3;                  // = ceil((128by-2)/3)
    const int b_hi = (128 * by + 125) / 3;
    for (int b = b_lo + warp; b <= b_hi; b += 8) {
        const float* qb = g_qk + (size_t)3 * b * NQK;
        float v[9];
#pragma unroll
        for (int u = 0; u < 9; ++u) v[u] = 0.f;
        for (int h = lane; h < DH_SZ; h += 32) {
            float q0 = qb[h];
            float q1 = qb[NQK + h];
            float q2 = qb[2 * NQK + h];
            float k0 = qb[DH_SZ + h];
            float k1 = qb[NQK + DH_SZ + h];
            float k2 = qb[2 * NQK + DH_SZ + h];
            v[0] += q0 * k0; v[1] += q0 * k1; v[2] += q0 * k2;
            v[3] += q1 * k0; v[4] += q1 * k1; v[5] += q1 * k2;
            v[6] += q2 * k0; v[7] += q2 * k1; v[8] += q2 * k2;
        }
#pragma unroll
        for (int off = 16; off > 0; off >>= 1)
#pragma unroll
            for (int u = 0; u < 9; ++u)
                v[u] += __shfl_xor_sync(0xffffffffu, v[u], off);

        if (lane == 0) {
            float s0 = 0.f, s1 = 0.f, s2 = 0.f;
#pragma unroll
            for (int p = 0; p < 8; ++p) {
                s0 += g_spart[p * MTOT + 3 * b];
                s1 += g_spart[p * MTOT + 3 * b + 1];
                s2 += g_spart[p * MTOT + 3 * b + 2];
            }
            float attn[3] = {0.f, 0.f, 0.f};
#pragma unroll
            for (int i = 0; i < 3; ++i) {
                float a0 = v[i * 3 + 0], a1 = v[i * 3 + 1], a2 = v[i * 3 + 2];
                float m = fmaxf(a0, fmaxf(a1, a2));
                float e0 = expf(a0 - m), e1 = expf(a1 - m), e2 = expf(a2 - m);
                float inv = 1.f / (e0 + e1 + e2);
                attn[0] += e0 * inv; attn[1] += e1 * inv; attn[2] += e2 * inv;
            }
            out[b] = (attn[0] * s0 + attn[1] * s1 + attn[2] * s2) * (1.f / 3.f);
        }
    }
}

// ---------------------------------------------------------------------------
// Launch
// ---------------------------------------------------------------------------
extern "C" void kernel_launch(void* const* d_in, const int* in_sizes, int n_in,
                              void* d_out, int out_size) {
    const float* x   = (const float*)d_in[0];
    const float* Wq  = (const float*)d_in[1];
    const float* Wk  = (const float*)d_in[2];
    const float* Wv  = (const float*)d_in[3];
    const float* Wfc = (const float*)d_in[4];
    float* out = (float*)d_out;

    cudaFuncSetAttribute(gemm_kernel, cudaFuncAttributeMaxDynamicSharedMemorySize, SMEM_TOTAL);

    clear_kernel<<<1, NBLK>>>();
    split_w_kernel<<<(NQK * D_SZ) / 256, 256>>>(Wq, Wk);
    wvf_kernel<<<D_SZ / 256, 256>>>(Wv, Wfc);
    split_x_kernel<<<((size_t)MTOT * D_SZ) / (256 * 8), 256>>>(x);
    gemm_kernel<<<dim3(NQK / 128, MTOT / 128), 256, SMEM_TOTAL>>>(out);
}

// round 17
// speedup vs baseline: 1.2096x; 1.2096x over previous
#include <cuda_runtime.h>
#include <cuda_bf16.h>
#include <cstdint>
#include <cstddef>

// Problem sizes (fixed)
#define B_SZ   16384
#define M_SZ   3
#define D_SZ   2048
#define DH_SZ  1024
#define MTOT   (B_SZ * M_SZ)   // 49152 rows
#define NQK    (2 * DH_SZ)     // 2048 output cols (q | k)

// ---------------------------------------------------------------------------
// Device scratch
// ---------------------------------------------------------------------------
__device__ __nv_bfloat16 g_xhi[(size_t)MTOT * D_SZ];
__device__ __nv_bfloat16 g_xlo[(size_t)MTOT * D_SZ];
__device__ __nv_bfloat16 g_whi[(size_t)NQK * D_SZ];    // [n][k], n<1024 -> Wq, else Wk
__device__ __nv_bfloat16 g_wlo[(size_t)NQK * D_SZ];
__device__ float         g_qk [(size_t)MTOT * NQK];
__device__ float         g_wvf[D_SZ];
__device__ float         g_spart[8 * MTOT];            // partial s = x . wvf

// ---------------------------------------------------------------------------
// Helpers
// ---------------------------------------------------------------------------
__device__ __forceinline__ void cp16(uint32_t dst, const void* src) {
    asm volatile("cp.async.cg.shared.global [%0], [%1], 16;\n" :: "r"(dst), "l"(src));
}
#define CP_COMMIT()  asm volatile("cp.async.commit_group;\n")
#define CP_WAIT(n)   asm volatile("cp.async.wait_group %0;\n" :: "n"(n))

#define LDSM4(R, addr)                                                          \
    asm volatile("ldmatrix.sync.aligned.m8n8.x4.shared.b16 {%0,%1,%2,%3}, [%4];"\
        : "=r"((R)[0]), "=r"((R)[1]), "=r"((R)[2]), "=r"((R)[3]) : "r"(addr))

#define MMA_BF16(C, A0, A1, A2, A3, B0, B1)                                     \
    asm volatile(                                                               \
        "mma.sync.aligned.m16n8k16.row.col.f32.bf16.bf16.f32 "                  \
        "{%0,%1,%2,%3}, {%4,%5,%6,%7}, {%8,%9}, {%0,%1,%2,%3};\n"               \
        : "+f"(C[0]), "+f"(C[1]), "+f"(C[2]), "+f"(C[3])                        \
        : "r"(A0), "r"(A1), "r"(A2), "r"(A3), "r"(B0), "r"(B1))

// ---------------------------------------------------------------------------
// Kernel 1: split concatenated weights [Wq;Wk] into bf16 hi/lo
// ---------------------------------------------------------------------------
__global__ void split_w_kernel(const float* __restrict__ Wq, const float* __restrict__ Wk) {
    int i = blockIdx.x * 256 + threadIdx.x;
    int n = i >> 11;
    int k = i & 2047;
    float w = (n < DH_SZ) ? Wq[(size_t)n * D_SZ + k]
                          : Wk[(size_t)(n - DH_SZ) * D_SZ + k];
    __nv_bfloat16 h = __float2bfloat16(w);
    g_whi[i] = h;
    g_wlo[i] = __float2bfloat16(w - __bfloat162float(h));
}

// ---------------------------------------------------------------------------
// Kernel 2: wvf[d] = sum_v Wfc[v] * Wv[v][d]
// ---------------------------------------------------------------------------
__global__ void wvf_kernel(const float* __restrict__ Wv, const float* __restrict__ Wfc) {
    int d = blockIdx.x * 256 + threadIdx.x;
    float acc = 0.f;
    for (int v = 0; v < 512; ++v)
        acc += Wfc[v] * Wv[(size_t)v * D_SZ + d];
    g_wvf[d] = acc;
}

// ---------------------------------------------------------------------------
// Kernel 3: split x into bf16 hi/lo + partial s = x . wvf per 256-float block
// ---------------------------------------------------------------------------
__global__ void split_x_kernel(const float* __restrict__ x) {
    size_t i = ((size_t)blockIdx.x * 256 + threadIdx.x) * 8;
    int lane = threadIdx.x & 31;
    float4 v0 = *(const float4*)(x + i);
    float4 v1 = *(const float4*)(x + i + 4);
    float f[8] = {v0.x, v0.y, v0.z, v0.w, v1.x, v1.y, v1.z, v1.w};
    union { uint4 u; __nv_bfloat16 b[8]; } H, L;
    int k0 = (int)(i & 2047);
    float part = 0.f;
#pragma unroll
    for (int j = 0; j < 8; ++j) {
        __nv_bfloat16 h = __float2bfloat16(f[j]);
        H.b[j] = h;
        L.b[j] = __float2bfloat16(f[j] - __bfloat162float(h));
        part += f[j] * g_wvf[k0 + j];
    }
    *(uint4*)(g_xhi + i) = H.u;
    *(uint4*)(g_xlo + i) = L.u;
#pragma unroll
    for (int off = 16; off > 0; off >>= 1)
        part += __shfl_xor_sync(0xffffffffu, part, off);
    if (lane == 0) {
        int row = (int)(i >> 11);
        g_spart[(k0 >> 8) * MTOT + row] = part;
    }
}

// ---------------------------------------------------------------------------
// Kernel 4: GEMM  QK[49152,2048] = X * W^T  (3-pass bf16 split, mma.sync)
//   R15 structure exactly (CTA 128x128, BK=32, 8 warps 4Mx2N, warp 32x64,
//   mid-iteration fill, 3-stage cp.async) + ONE change:
//   LDSM/MMA interleaved inside each K16 half (first MMA after 4 LDSMs
//   instead of 12). Epilogue = R15's pure store (no finisher).
// ---------------------------------------------------------------------------
#define BK          32
#define NKT         (D_SZ / BK)              // 64
#define TILE_B      (128 * 64)               // one tile: 128 rows x 64B (32 bf16)
#define STAGE_B     (4 * TILE_B)             // Ahi, Alo, Bhi, Blo = 32768 B
#define SMEM_TOTAL  (3 * STAGE_B)            // 98304 B

__device__ __forceinline__ uint32_t swz(int r, int c) {
    return (uint32_t)(r * 64 + ((c ^ ((r >> 1) & 3)) << 4));
}

__global__ void __launch_bounds__(256, 2) gemm_kernel() {
    extern __shared__ __align__(16) char smem[];
    uint32_t sbase;
    asm("{ .reg .u64 t; cvta.to.shared.u64 t, %1; cvt.u32.u64 %0, t; }" : "=r"(sbase) : "l"(smem));

    const int tid  = threadIdx.x;
    const int warp = tid >> 5;
    const int lane = tid & 31;
    const int wm   = warp & 3;             // warp row tile (32 rows)
    const int wn   = warp >> 2;            // warp col tile (64 cols)
    const int row0 = blockIdx.y * 128;
    const int col0 = blockIdx.x * 128;
    const int g    = lane >> 2;
    const int t2   = (lane & 3) * 2;

    const int rsubA = (lane & 7) + ((lane >> 3) & 1) * 8;
    const int cA    = lane >> 4;
    const int nsubB = (lane & 7) + ((lane >> 4) & 1) * 8;
    const int cB    = (lane >> 3) & 1;

    float c[2][8][4];
#pragma unroll
    for (int i = 0; i < 2; ++i)
#pragma unroll
        for (int j = 0; j < 8; ++j)
#pragma unroll
            for (int u = 0; u < 4; ++u) c[i][j][u] = 0.f;

    auto fill = [&](int s, int kt) {
        const int k0 = kt * BK;
        const uint32_t st = sbase + s * STAGE_B;
#pragma unroll
        for (int v = 0; v < 2; ++v) {                 // A hi+lo
            int idx = tid + v * 256;
            int r = idx >> 2, cc = idx & 3;
            uint32_t so = st + swz(r, cc);
            size_t go = (size_t)(row0 + r) * D_SZ + k0 + cc * 8;
            cp16(so,          g_xhi + go);
            cp16(so + TILE_B, g_xlo + go);
        }
#pragma unroll
        for (int v = 0; v < 2; ++v) {                 // B hi+lo
            int idx = tid + v * 256;
            int r = idx >> 2, cc = idx & 3;
            uint32_t so = st + 2 * TILE_B + swz(r, cc);
            size_t go = (size_t)(col0 + r) * D_SZ + k0 + cc * 8;
            cp16(so,          g_whi + go);
            cp16(so + TILE_B, g_wlo + go);
        }
    };

    // One K16 half with LDSM/MMA interleaved (first MMA after 4 LDSMs).
    auto compute_half = [&](int s, int c0) {
        const uint32_t sA = sbase + s * STAGE_B;
        const uint32_t sB = sA + 2 * TILE_B;
        uint32_t ahi[2][4], alo[2][4], bhi[8][2], blo[8][2];

        auto loadA = [&](int i) {
            int r = wm * 32 + i * 16 + rsubA;
            uint32_t addr = sA + swz(r, c0 + cA);
            LDSM4(ahi[i], addr);
            LDSM4(alo[i], addr + TILE_B);
        };
        auto loadB = [&](int jp) {
            int n = wn * 64 + jp * 16 + nsubB;
            uint32_t addr = sB + swz(n, c0 + cB);
            uint32_t th[4], tl[4];
            LDSM4(th, addr);
            LDSM4(tl, addr + TILE_B);
            bhi[2 * jp][0] = th[0]; bhi[2 * jp][1] = th[1];
            bhi[2 * jp + 1][0] = th[2]; bhi[2 * jp + 1][1] = th[3];
            blo[2 * jp][0] = tl[0]; blo[2 * jp][1] = tl[1];
            blo[2 * jp + 1][0] = tl[2]; blo[2 * jp + 1][1] = tl[3];
        };
        auto mma3 = [&](int i, int j) {
            MMA_BF16(c[i][j], ahi[i][0], ahi[i][1], ahi[i][2], ahi[i][3], bhi[j][0], bhi[j][1]);
            MMA_BF16(c[i][j], ahi[i][0], ahi[i][1], ahi[i][2], ahi[i][3], blo[j][0], blo[j][1]);
            MMA_BF16(c[i][j], alo[i][0], alo[i][1], alo[i][2], alo[i][3], bhi[j][0], bhi[j][1]);
        };

        loadA(0);
        loadB(0);
        mma3(0, 0); mma3(0, 1);
        loadB(1);
        mma3(0, 2); mma3(0, 3);
        loadA(1);
        mma3(1, 0); mma3(1, 1); mma3(1, 2); mma3(1, 3);
        loadB(2);
        mma3(0, 4); mma3(0, 5); mma3(1, 4); mma3(1, 5);
        loadB(3);
        mma3(0, 6); mma3(0, 7); mma3(1, 6); mma3(1, 7);
    };

    // 3-stage pipeline (R15 schedule)
    fill(0, 0); CP_COMMIT();
    fill(1, 1); CP_COMMIT();

    {   // co-resident CTA desync (R10 win)
        int bid = blockIdx.y * gridDim.x + blockIdx.x;
        if ((bid / 148) & 1) __nanosleep(1000);
    }

    for (int kt = 0; kt < NKT; ++kt) {
        CP_WAIT(1);
        __syncthreads();
        compute_half(kt % 3, 0);                        // HMMA right after barrier
        if (kt + 2 < NKT) fill((kt + 2) % 3, kt + 2);   // LSU burst mid-iteration
        CP_COMMIT();
        compute_half(kt % 3, 2);
    }

    // Epilogue: store accumulators (R15 exact)
#pragma unroll
    for (int i = 0; i < 2; ++i) {
        int r = row0 + wm * 32 + i * 16 + g;
#pragma unroll
        for (int j = 0; j < 8; ++j) {
            int cb = col0 + wn * 64 + j * 8 + t2;
            *(float2*)(g_qk + (size_t)r * NQK + cb)       = make_float2(c[i][j][0], c[i][j][1]);
            *(float2*)(g_qk + (size_t)(r + 8) * NQK + cb) = make_float2(c[i][j][2], c[i][j][3]);
        }
    }
}

// ---------------------------------------------------------------------------
// Kernel 5: Gram + softmax + output. One warp per batch (R15 exact).
// ---------------------------------------------------------------------------
__global__ void gram_kernel(float* __restrict__ out) {
    int b = blockIdx.x * 8 + (threadIdx.x >> 5);
    int lane = threadIdx.x & 31;

    const float* qb = g_qk + (size_t)3 * b * NQK;
    float v[9];
#pragma unroll
    for (int u = 0; u < 9; ++u) v[u] = 0.f;

    for (int h = lane; h < DH_SZ; h += 32) {
        float q0 = qb[h];
        float q1 = qb[NQK + h];
        float q2 = qb[2 * NQK + h];
        float k0 = qb[DH_SZ + h];
        float k1 = qb[NQK + DH_SZ + h];
        float k2 = qb[2 * NQK + DH_SZ + h];
        v[0] += q0 * k0; v[1] += q0 * k1; v[2] += q0 * k2;
        v[3] += q1 * k0; v[4] += q1 * k1; v[5] += q1 * k2;
        v[6] += q2 * k0; v[7] += q2 * k1; v[8] += q2 * k2;
    }
#pragma unroll
    for (int off = 16; off > 0; off >>= 1)
#pragma unroll
        for (int u = 0; u < 9; ++u)
            v[u] += __shfl_xor_sync(0xffffffffu, v[u], off);

    if (lane == 0) {
        float s0 = 0.f, s1 = 0.f, s2 = 0.f;
#pragma unroll
        for (int p = 0; p < 8; ++p) {
            s0 += g_spart[p * MTOT + 3 * b];
            s1 += g_spart[p * MTOT + 3 * b + 1];
            s2 += g_spart[p * MTOT + 3 * b + 2];
        }
        float attn[3] = {0.f, 0.f, 0.f};
#pragma unroll
        for (int i = 0; i < 3; ++i) {
            float a0 = v[i * 3 + 0], a1 = v[i * 3 + 1], a2 = v[i * 3 + 2];
            float m = fmaxf(a0, fmaxf(a1, a2));
            float e0 = expf(a0 - m), e1 = expf(a1 - m), e2 = expf(a2 - m);
            float inv = 1.f / (e0 + e1 + e2);
            attn[0] += e0 * inv; attn[1] += e1 * inv; attn[2] += e2 * inv;
        }
        out[b] = (attn[0] * s0 + attn[1] * s1 + attn[2] * s2) * (1.f / 3.f);
    }
}

// ---------------------------------------------------------------------------
// Launch
// ---------------------------------------------------------------------------
extern "C" void kernel_launch(void* const* d_in, const int* in_sizes, int n_in,
                              void* d_out, int out_size) {
    const float* x   = (const float*)d_in[0];
    const float* Wq  = (const float*)d_in[1];
    const float* Wk  = (const float*)d_in[2];
    const float* Wv  = (const float*)d_in[3];
    const float* Wfc = (const float*)d_in[4];
    float* out = (float*)d_out;

    cudaFuncSetAttribute(gemm_kernel, cudaFuncAttributeMaxDynamicSharedMemorySize, SMEM_TOTAL);

    split_w_kernel<<<(NQK * D_SZ) / 256, 256>>>(Wq, Wk);
    wvf_kernel<<<D_SZ / 256, 256>>>(Wv, Wfc);
    split_x_kernel<<<((size_t)MTOT * D_SZ) / (256 * 8), 256>>>(x);
    gemm_kernel<<<dim3(NQK / 128, MTOT / 128), 256, SMEM_TOTAL>>>();
    gram_kernel<<<B_SZ / 8, 256>>>(out);
}